// round 8
// baseline (speedup 1.0000x reference)
#include <cuda_runtime.h>
#include <cuda_bf16.h>
#include <stdint.h>

// SparseMixerV2 forward — warp-private double-buffered cp.async pipelines,
// 4-way ILP-split reductions (no serial 64-deep FADD/SEL chains).
//   sel = argmax(logits) (first occurrence)
//   masked_j iff (m - l_j)/max(|l_j|, m) > 0.2   [division-free: 0.2*f + l < m]
//   multiplier = (0.3333+0.6667) / sum_unmasked exp(l_j - m)
// rand_u is provably dead (sel == argmax(masked_gates) always).
//
// One warp per block, one row per thread, 32-row / 8KB tiles, 2-deep ring in
// static smem, 13 independent warp-pipelines per SM. XOR swizzle write via
// cp.async + XOR-rotated LDS.128 read (self-de-swizzling, conflict-free).

#define E 64
#define TPB 32
#define TILE 32
#define BUF_FLOATS (TILE * E)          // 2048 floats = 8KB
#define LOG2E 1.4426950408889634f

__device__ __forceinline__ void prefetch_tile(const float* __restrict__ logits,
                                              float* __restrict__ buf,
                                              int tile, int lane)
{
    const float4* g = reinterpret_cast<const float4*>(logits + (size_t)tile * TILE * E);
    #pragma unroll
    for (int i = 0; i < 16; i++) {
        int idx  = lane + i * 32;
        int row  = idx >> 4;
        int col  = idx & 15;
        int slot = col ^ (row & 15);       // XOR swizzle
        uint32_t dst = (uint32_t)__cvta_generic_to_shared(buf + row * E + slot * 4);
        asm volatile("cp.async.cg.shared.global [%0], [%1], 16;"
                     :: "r"(dst), "l"(g + idx) : "memory");
    }
    asm volatile("cp.async.commit_group;" ::: "memory");
}

__global__ void __launch_bounds__(TPB)
sparsemixer_warp(const float* __restrict__ logits,
                 float* __restrict__ out,      // [0,N): sel, [N,2N): mult, [2N]: 0
                 int N, int out_size)
{
    __shared__ float smem[2 * BUF_FLOATS];     // 16KB static
    const int t = threadIdx.x;

    if (blockIdx.x == 0 && t == 0 && out_size > 2 * N)
        out[2 * N] = 0.0f;                     // balance_loss

    const int numTiles = N / TILE;
    int tile = blockIdx.x;
    if (tile >= numTiles) return;

    prefetch_tile(logits, smem, tile, t);      // slot 0

    const uint32_t sbase = (uint32_t)__cvta_generic_to_shared(smem);
    const uint32_t rowrot0 = sbase + (uint32_t)t * 256u + ((uint32_t)(t & 15) << 4);

    int bufIdx = 0;
    for (; tile < numTiles; tile += gridDim.x) {
        const int nextTile = tile + gridDim.x;
        if (nextTile < numTiles) {
            prefetch_tile(logits, smem + (bufIdx ^ 1) * BUF_FLOATS, nextTile, t);
            asm volatile("cp.async.wait_group 1;" ::: "memory");
        } else {
            asm volatile("cp.async.wait_group 0;" ::: "memory");
        }
        __syncwarp();

        // ---- gather my row: 16 LDS.128 (XOR address self-de-swizzles) ----
        float4 v[16];
        const uint32_t rb = rowrot0 + (uint32_t)bufIdx * (BUF_FLOATS * 4u);
        #pragma unroll
        for (int c = 0; c < 16; c++) {
            float4 tmp;
            asm volatile("ld.shared.v4.f32 {%0,%1,%2,%3}, [%4];"
                         : "=f"(tmp.x), "=f"(tmp.y), "=f"(tmp.z), "=f"(tmp.w)
                         : "r"(rb ^ ((uint32_t)c << 4)));
            v[c] = tmp;
        }

        // ---- pass 1: row max, 4 parallel partials ----
        float m0 = fmaxf(fmaxf(v[0].x,  v[0].y),  fmaxf(v[0].z,  v[0].w));
        float m1 = fmaxf(fmaxf(v[1].x,  v[1].y),  fmaxf(v[1].z,  v[1].w));
        float m2 = fmaxf(fmaxf(v[2].x,  v[2].y),  fmaxf(v[2].z,  v[2].w));
        float m3 = fmaxf(fmaxf(v[3].x,  v[3].y),  fmaxf(v[3].z,  v[3].w));
        #pragma unroll
        for (int c = 4; c < 16; c += 4) {
            m0 = fmaxf(m0, fmaxf(fmaxf(v[c+0].x, v[c+0].y), fmaxf(v[c+0].z, v[c+0].w)));
            m1 = fmaxf(m1, fmaxf(fmaxf(v[c+1].x, v[c+1].y), fmaxf(v[c+1].z, v[c+1].w)));
            m2 = fmaxf(m2, fmaxf(fmaxf(v[c+2].x, v[c+2].y), fmaxf(v[c+2].z, v[c+2].w)));
            m3 = fmaxf(m3, fmaxf(fmaxf(v[c+3].x, v[c+3].y), fmaxf(v[c+3].z, v[c+3].w)));
        }
        const float m = fmaxf(fmaxf(m0, m1), fmaxf(m2, m3));

        const float c0 = -m * LOG2E;           // exp(l-m) = ex2(l*log2e + c0)

        // ---- pass 2: 4 independent chains (quad-groups), then merge ----
        // chain k owns quads [4k, 4k+4), scans DESCENDING -> its sel_k ends as
        // the smallest matching index in its range (or 1024). Global first
        // occurrence = min over chains (first occurrence == smallest index
        // with x == m).
        float s0 = 0.f, s1 = 0.f, s2 = 0.f, s3 = 0.f;
        int   e0 = 1024, e1 = 1024, e2 = 1024, e3 = 1024;

        #define SM_ELEM(S, SEL, X, IDX) {                                        \
            const float x_ = (X);                                                \
            const float f_ = fmaxf(fabsf(x_), m);                                \
            float ex_;                                                           \
            asm("ex2.approx.f32 %0, %1;" : "=f"(ex_) : "f"(fmaf(x_, LOG2E, c0)));\
            if (fmaf(0.2f, f_, x_) >= m) S += ex_;                               \
            if (x_ == m) SEL = (IDX); }

        #define SM_QUAD(S, SEL, J) {                                             \
            SM_ELEM(S, SEL, v[J].w, 4*(J)+3)                                     \
            SM_ELEM(S, SEL, v[J].z, 4*(J)+2)                                     \
            SM_ELEM(S, SEL, v[J].y, 4*(J)+1)                                     \
            SM_ELEM(S, SEL, v[J].x, 4*(J)+0) }

        #pragma unroll
        for (int j = 3; j >= 0; j--) {         // interleave the 4 chains
            SM_QUAD(s0, e0, j)
            SM_QUAD(s1, e1, j + 4)
            SM_QUAD(s2, e2, j + 8)
            SM_QUAD(s3, e3, j + 12)
        }
        #undef SM_QUAD
        #undef SM_ELEM

        const float s  = (s0 + s1) + (s2 + s3);
        const int   sel = min(min(e0, e1), min(e2, e3));

        const int row = tile * TILE + t;
        const float mf1 = 0.3333f + 0.6667f;   // mask_for_one (always true-branch)
        out[row]     = (float)sel;
        out[N + row] = mf1 / s;

        __syncwarp();
        bufIdx ^= 1;
    }
}

extern "C" void kernel_launch(void* const* d_in, const int* in_sizes, int n_in,
                              void* d_out, int out_size)
{
    const float* logits = (const float*)d_in[0];   // d_in[1] = rand_u: dead
    float* out = (float*)d_out;

    const int N = in_sizes[0] / E;                 // 1048576
    const int numTiles = N / TILE;                 // 32768

    int blocks = 13 * 148;                         // 13 warp-pipelines/SM (208KB smem, safe)
    if (blocks > numTiles) blocks = numTiles;

    sparsemixer_warp<<<blocks, TPB>>>(logits, out, N, out_size);
}

// round 11
// speedup vs baseline: 1.1196x; 1.1196x over previous
#include <cuda_runtime.h>
#include <cuda_bf16.h>
#include <stdint.h>

// SparseMixerV2 forward — warp-private double-buffered cp.async pipelines,
// instruction-minimized inner loop.
//   sel = argmax(logits) (first occurrence)
//   keep_j iff (m - l_j)/max(|l_j|, m) <= 0.2  ==  l_j >= T,
//       T = m*0.8 (m>=0) else m*1.25          [exact case analysis]
//   multiplier = (0.3333+0.6667) / sum_keep exp(l_j - m)
// rand_u is provably dead (sel == argmax(masked_gates) always).
//
// One warp per block, one row per thread, 32-row / 8KB tiles, 2-deep ring in
// static smem, 12 independent warp-pipelines per SM. XOR swizzle write via
// cp.async + XOR-rotated LDS.128 read (self-de-swizzling, conflict-free).
// Argmax via per-quad maxes + one dynamic LDS.128 re-read of the winning quad.

#define E 64
#define TPB 32
#define TILE 32
#define BUF_FLOATS (TILE * E)          // 2048 floats = 8KB
#define LOG2E 1.4426950408889634f

__device__ __forceinline__ void prefetch_tile(const float* __restrict__ logits,
                                              float* __restrict__ buf,
                                              int tile, int lane)
{
    const float4* g = reinterpret_cast<const float4*>(logits + (size_t)tile * TILE * E);
    #pragma unroll
    for (int i = 0; i < 16; i++) {
        int idx  = lane + i * 32;
        int row  = idx >> 4;
        int col  = idx & 15;
        int slot = col ^ (row & 15);       // XOR swizzle
        uint32_t dst = (uint32_t)__cvta_generic_to_shared(buf + row * E + slot * 4);
        asm volatile("cp.async.cg.shared.global [%0], [%1], 16;"
                     :: "r"(dst), "l"(g + idx) : "memory");
    }
    asm volatile("cp.async.commit_group;" ::: "memory");
}

__global__ void __launch_bounds__(TPB)
sparsemixer_warp(const float* __restrict__ logits,
                 float* __restrict__ out,      // [0,N): sel, [N,2N): mult, [2N]: 0
                 int N, int out_size)
{
    __shared__ float smem[2 * BUF_FLOATS];     // 16KB static
    const int t = threadIdx.x;

    if (blockIdx.x == 0 && t == 0 && out_size > 2 * N)
        out[2 * N] = 0.0f;                     // balance_loss

    const int numTiles = N / TILE;
    int tile = blockIdx.x;
    if (tile >= numTiles) return;

    prefetch_tile(logits, smem, tile, t);      // slot 0

    const uint32_t sbase = (uint32_t)__cvta_generic_to_shared(smem);
    const uint32_t rowrot0 = sbase + (uint32_t)t * 256u + ((uint32_t)(t & 15) << 4);

    int bufIdx = 0;
    for (; tile < numTiles; tile += gridDim.x) {
        const int nextTile = tile + gridDim.x;
        if (nextTile < numTiles) {
            prefetch_tile(logits, smem + (bufIdx ^ 1) * BUF_FLOATS, nextTile, t);
            asm volatile("cp.async.wait_group 1;" ::: "memory");
        } else {
            asm volatile("cp.async.wait_group 0;" ::: "memory");
        }
        __syncwarp();

        // ---- gather my row: 16 LDS.128 (XOR address self-de-swizzles) ----
        float4 v[16];
        const uint32_t rb = rowrot0 + (uint32_t)bufIdx * (BUF_FLOATS * 4u);
        #pragma unroll
        for (int c = 0; c < 16; c++) {
            float4 tmp;
            asm volatile("ld.shared.v4.f32 {%0,%1,%2,%3}, [%4];"
                         : "=f"(tmp.x), "=f"(tmp.y), "=f"(tmp.z), "=f"(tmp.w)
                         : "r"(rb ^ ((uint32_t)c << 4)));
            v[c] = tmp;
        }

        // ---- pass 1: per-quad maxes, then row max ----
        float qm[16];
        #pragma unroll
        for (int c = 0; c < 16; c++)
            qm[c] = fmaxf(fmaxf(v[c].x, v[c].y), fmaxf(v[c].z, v[c].w));
        float a0 = fmaxf(fmaxf(qm[0], qm[1]),  fmaxf(qm[2],  qm[3]));
        float a1 = fmaxf(fmaxf(qm[4], qm[5]),  fmaxf(qm[6],  qm[7]));
        float a2 = fmaxf(fmaxf(qm[8], qm[9]),  fmaxf(qm[10], qm[11]));
        float a3 = fmaxf(fmaxf(qm[12], qm[13]), fmaxf(qm[14], qm[15]));
        const float m = fmaxf(fmaxf(a0, a1), fmaxf(a2, a3));

        // keep iff x >= T  (exact closed form of the jitter mask)
        const float T  = m * (m >= 0.0f ? 0.8f : 1.25f);
        const float c0 = -m * LOG2E;           // exp(l-m) = ex2(l*log2e + c0)

        // ---- pass 2: masked exp-sum only (4 inst/element), 2-way split ----
        float sa = 0.0f, sb = 0.0f;
        #define SM_ELEM(S, X) {                                                  \
            const float x_ = (X);                                                \
            float ex_;                                                           \
            asm("ex2.approx.f32 %0, %1;" : "=f"(ex_) : "f"(fmaf(x_, LOG2E, c0)));\
            if (x_ >= T) S += ex_; }
        #pragma unroll
        for (int j = 0; j < 16; j += 2) {
            SM_ELEM(sa, v[j].x)   SM_ELEM(sa, v[j].y)
            SM_ELEM(sa, v[j].z)   SM_ELEM(sa, v[j].w)
            SM_ELEM(sb, v[j+1].x) SM_ELEM(sb, v[j+1].y)
            SM_ELEM(sb, v[j+1].z) SM_ELEM(sb, v[j+1].w)
        }
        #undef SM_ELEM
        const float s = sa + sb;

        // ---- argmax: first quad attaining m (descending scan -> smallest j) ----
        int selq = 0;
        #pragma unroll
        for (int j = 15; j >= 0; j--)
            if (qm[j] == m) selq = j;

        // re-read winning quad (dynamic XOR address, still conflict-free)
        float4 q;
        asm volatile("ld.shared.v4.f32 {%0,%1,%2,%3}, [%4];"
                     : "=f"(q.x), "=f"(q.y), "=f"(q.z), "=f"(q.w)
                     : "r"(rb ^ ((uint32_t)selq << 4)));
        int e = 3;
        if (q.z == m) e = 2;
        if (q.y == m) e = 1;
        if (q.x == m) e = 0;
        const int sel = 4 * selq + e;

        const int row = tile * TILE + t;
        const float mf1 = 0.3333f + 0.6667f;   // mask_for_one (always true-branch)
        out[row]     = (float)sel;
        out[N + row] = mf1 / s;

        __syncwarp();
        bufIdx ^= 1;
    }
}

extern "C" void kernel_launch(void* const* d_in, const int* in_sizes, int n_in,
                              void* d_out, int out_size)
{
    const float* logits = (const float*)d_in[0];   // d_in[1] = rand_u: dead
    float* out = (float*)d_out;

    const int N = in_sizes[0] / E;                 // 1048576
    const int numTiles = N / TILE;                 // 32768

    int blocks = 12 * 148;                         // 12 warp-pipelines/SM (known-best cfg)
    if (blocks > numTiles) blocks = numTiles;

    sparsemixer_warp<<<blocks, TPB>>>(logits, out, N, out_size);
}

// round 13
// speedup vs baseline: 1.1217x; 1.0020x over previous
#include <cuda_runtime.h>
#include <cuda_bf16.h>
#include <stdint.h>

// SparseMixerV2 forward — warp-private double-buffered cp.async pipelines,
// instruction-minimized inner loop.
//   sel = argmax(logits) (first occurrence)
//   keep_j iff (m - l_j)/max(|l_j|, m) <= 0.2  ==  l_j >= T,
//       T = m*0.8 (m>=0) else m*1.25          [exact case analysis]
//   multiplier = (0.3333+0.6667) / sum_keep exp(l_j - m)
// rand_u is provably dead (sel == argmax(masked_gates) always).
//
// One warp per block, one row per thread, 32-row / 8KB tiles, 2-deep ring in
// static smem, 12 independent warp-pipelines per SM. XOR swizzle write via
// cp.async + XOR-rotated LDS.128 read (self-de-swizzling, conflict-free).
// Argmax via per-quad maxes + one dynamic LDS.128 re-read of the winning quad.

#define E 64
#define TPB 32
#define TILE 32
#define BUF_FLOATS (TILE * E)          // 2048 floats = 8KB
#define LOG2E 1.4426950408889634f

__device__ __forceinline__ void prefetch_tile(const float* __restrict__ logits,
                                              float* __restrict__ buf,
                                              int tile, int lane)
{
    const float4* g = reinterpret_cast<const float4*>(logits + (size_t)tile * TILE * E);
    #pragma unroll
    for (int i = 0; i < 16; i++) {
        int idx  = lane + i * 32;
        int row  = idx >> 4;
        int col  = idx & 15;
        int slot = col ^ (row & 15);       // XOR swizzle
        uint32_t dst = (uint32_t)__cvta_generic_to_shared(buf + row * E + slot * 4);
        asm volatile("cp.async.cg.shared.global [%0], [%1], 16;"
                     :: "r"(dst), "l"(g + idx) : "memory");
    }
    asm volatile("cp.async.commit_group;" ::: "memory");
}

__global__ void __launch_bounds__(TPB)
sparsemixer_warp(const float* __restrict__ logits,
                 float* __restrict__ out,      // [0,N): sel, [N,2N): mult, [2N]: 0
                 int N, int out_size)
{
    __shared__ float smem[2 * BUF_FLOATS];     // 16KB static
    const int t = threadIdx.x;

    if (blockIdx.x == 0 && t == 0 && out_size > 2 * N)
        out[2 * N] = 0.0f;                     // balance_loss

    const int numTiles = N / TILE;
    int tile = blockIdx.x;
    if (tile >= numTiles) return;

    prefetch_tile(logits, smem, tile, t);      // slot 0

    const uint32_t sbase = (uint32_t)__cvta_generic_to_shared(smem);
    const uint32_t rowrot0 = sbase + (uint32_t)t * 256u + ((uint32_t)(t & 15) << 4);

    int bufIdx = 0;
    for (; tile < numTiles; tile += gridDim.x) {
        const int nextTile = tile + gridDim.x;
        if (nextTile < numTiles) {
            prefetch_tile(logits, smem + (bufIdx ^ 1) * BUF_FLOATS, nextTile, t);
            asm volatile("cp.async.wait_group 1;" ::: "memory");
        } else {
            asm volatile("cp.async.wait_group 0;" ::: "memory");
        }
        __syncwarp();

        // ---- gather my row: 16 LDS.128 (XOR address self-de-swizzles) ----
        float4 v[16];
        const uint32_t rb = rowrot0 + (uint32_t)bufIdx * (BUF_FLOATS * 4u);
        #pragma unroll
        for (int c = 0; c < 16; c++) {
            float4 tmp;
            asm volatile("ld.shared.v4.f32 {%0,%1,%2,%3}, [%4];"
                         : "=f"(tmp.x), "=f"(tmp.y), "=f"(tmp.z), "=f"(tmp.w)
                         : "r"(rb ^ ((uint32_t)c << 4)));
            v[c] = tmp;
        }

        // ---- pass 1: per-quad maxes, then row max ----
        float qm[16];
        #pragma unroll
        for (int c = 0; c < 16; c++)
            qm[c] = fmaxf(fmaxf(v[c].x, v[c].y), fmaxf(v[c].z, v[c].w));
        float a0 = fmaxf(fmaxf(qm[0], qm[1]),  fmaxf(qm[2],  qm[3]));
        float a1 = fmaxf(fmaxf(qm[4], qm[5]),  fmaxf(qm[6],  qm[7]));
        float a2 = fmaxf(fmaxf(qm[8], qm[9]),  fmaxf(qm[10], qm[11]));
        float a3 = fmaxf(fmaxf(qm[12], qm[13]), fmaxf(qm[14], qm[15]));
        const float m = fmaxf(fmaxf(a0, a1), fmaxf(a2, a3));

        // keep iff x >= T  (exact closed form of the jitter mask)
        const float T  = m * (m >= 0.0f ? 0.8f : 1.25f);
        const float c0 = -m * LOG2E;           // exp(l-m) = ex2(l*log2e + c0)

        // ---- pass 2: masked exp-sum only (4 inst/element), 2-way split ----
        float sa = 0.0f, sb = 0.0f;
        #define SM_ELEM(S, X) {                                                  \
            const float x_ = (X);                                                \
            float ex_;                                                           \
            asm("ex2.approx.f32 %0, %1;" : "=f"(ex_) : "f"(fmaf(x_, LOG2E, c0)));\
            if (x_ >= T) S += ex_; }
        #pragma unroll
        for (int j = 0; j < 16; j += 2) {
            SM_ELEM(sa, v[j].x)   SM_ELEM(sa, v[j].y)
            SM_ELEM(sa, v[j].z)   SM_ELEM(sa, v[j].w)
            SM_ELEM(sb, v[j+1].x) SM_ELEM(sb, v[j+1].y)
            SM_ELEM(sb, v[j+1].z) SM_ELEM(sb, v[j+1].w)
        }
        #undef SM_ELEM
        const float s = sa + sb;

        // ---- argmax: first quad attaining m (descending scan -> smallest j) ----
        int selq = 0;
        #pragma unroll
        for (int j = 15; j >= 0; j--)
            if (qm[j] == m) selq = j;

        // re-read winning quad (dynamic XOR address, still conflict-free)
        float4 q;
        asm volatile("ld.shared.v4.f32 {%0,%1,%2,%3}, [%4];"
                     : "=f"(q.x), "=f"(q.y), "=f"(q.z), "=f"(q.w)
                     : "r"(rb ^ ((uint32_t)selq << 4)));
        int e = 3;
        if (q.z == m) e = 2;
        if (q.y == m) e = 1;
        if (q.x == m) e = 0;
        const int sel = 4 * selq + e;

        const int row = tile * TILE + t;
        const float mf1 = 0.3333f + 0.6667f;   // mask_for_one (always true-branch)
        out[row]     = (float)sel;
        out[N + row] = mf1 / s;

        __syncwarp();
        bufIdx ^= 1;
    }
}

extern "C" void kernel_launch(void* const* d_in, const int* in_sizes, int n_in,
                              void* d_out, int out_size)
{
    const float* logits = (const float*)d_in[0];   // d_in[1] = rand_u: dead
    float* out = (float*)d_out;

    const int N = in_sizes[0] / E;                 // 1048576
    const int numTiles = N / TILE;                 // 32768

    int blocks = 12 * 148;                         // 12 warp-pipelines/SM (known-best cfg)
    if (blocks > numTiles) blocks = numTiles;

    sparsemixer_warp<<<blocks, TPB>>>(logits, out, N, out_size);
}